// round 12
// baseline (speedup 1.0000x reference)
#include <cuda_runtime.h>
#include <cstdint>

#define SEQ 4096
#define HIDDEN 2048
#define NH 16
#define NKV 8
#define HD 128
#define WINDOW 1024
#define SCALING 0.08838834764831845f  /* 128^-0.5 */
#define SOFTCAP 50.0f

// ---------------- scratch (no allocations allowed) ----------------
__device__ float g_Q[SEQ * NH * HD];    // 32 MB
__device__ float g_K[SEQ * NKV * HD];   // 16 MB
__device__ float g_V[SEQ * NKV * HD];   // 16 MB
__device__ float g_AO[SEQ * NH * HD];   // 32 MB

__device__ __forceinline__ uint32_t f2tf32(float x) {
    uint32_t r;
    asm("cvt.rna.tf32.f32 %0, %1;" : "=r"(r) : "f"(x));
    return r;
}

__device__ __forceinline__ void cp16(uint32_t s, const void* g) {
    asm volatile("cp.async.cg.shared.global [%0], [%1], 16;" :: "r"(s), "l"(g) : "memory");
}
__device__ __forceinline__ void cp_commit() {
    asm volatile("cp.async.commit_group;" ::: "memory");
}
__device__ __forceinline__ void cp_wait1() {
    asm volatile("cp.async.wait_group 1;" ::: "memory");
}

// ---------------- cp.async 3-stage pipelined TF32 GEMM core ----------------
// C[128,128] block of C[M,N] = A[M,K] @ B[K,N], row-major.
// 256 thr (8 warps, 2x4), BK=32, 3-stage cp.async ring, ONE barrier/iter.
// As [m][k] stride 36 (mod32=4 -> A frags conflict-free)
// Bs [k][n] stride 136 (mod32=8 -> B frags conflict-free)
#define GAS_W 36
#define GBS_W 136
#define GA_STAGE (128 * GAS_W)          // 4608 words
#define GB_STAGE (32 * GBS_W)           // 4352 words
#define GSTAGE_W (GA_STAGE + GB_STAGE)  // 8960 words
#define GSMEM_BYTES (3 * GSTAGE_W * 4)  // 107520 B -> 2 CTAs/SM

__device__ __forceinline__ void gemm_core(
    const float* __restrict__ Ab,   // A + by*128*K
    const float* __restrict__ Bb,   // B + bx*128
    float* __restrict__ Cb,         // C + by*128*N + bx*128
    int N, int K)
{
    extern __shared__ float smem[];
    const uint32_t sb = (uint32_t)__cvta_generic_to_shared(smem);

    const int tid  = threadIdx.x;
    const int lane = tid & 31;
    const int gid  = lane >> 2;
    const int tig  = lane & 3;
    const int wid  = tid >> 5;
    const int wm0  = (wid >> 2) * 64;
    const int wn0  = (wid & 3) * 32;

    float c[4][4][4];
#pragma unroll
    for (int mi = 0; mi < 4; mi++)
#pragma unroll
        for (int ni = 0; ni < 4; ni++)
#pragma unroll
            for (int r = 0; r < 4; r++) c[mi][ni][r] = 0.f;

    const int KT = K / 32;

    auto issue = [&](int stg, int k0) {
        const uint32_t as = sb + (uint32_t)stg * GSTAGE_W * 4;
        const uint32_t bs = as + GA_STAGE * 4;
#pragma unroll
        for (int i = 0; i < 4; i++) {
            const int t = tid + i * 256;
            const int m = t >> 3, j = t & 7;
            cp16(as + (uint32_t)(m * GAS_W + 4 * j) * 4,
                 Ab + (size_t)m * K + k0 + 4 * j);
        }
#pragma unroll
        for (int i = 0; i < 4; i++) {
            const int t = tid + i * 256;
            const int r = t >> 5, cc = t & 31;
            cp16(bs + (uint32_t)(r * GBS_W + 4 * cc) * 4,
                 Bb + (size_t)(k0 + r) * N + 4 * cc);
        }
        cp_commit();
    };

    // prologue: two stages in flight
    issue(0, 0);
    issue(1, 32);

    int stg = 0;         // stage holding k-slab kt
    for (int kt = 0; kt < KT; kt++) {
        cp_wait1();          // slab kt resident (kt+1 still in flight)
        __syncthreads();     // visibility of kt to all threads; all warps past kt-1's reads

        // refill the slot consumed at iter kt-1 (stage (stg+2)%3).
        // Tail iterations wrap k0 to an already-consumed slab: keeps the
        // wait_group accounting uniform; the data is never read.
        {
            int stg2 = stg + 2; if (stg2 >= 3) stg2 -= 3;
            int knext = kt + 2; if (knext >= KT) knext -= KT;
            issue(stg2, knext * 32);
        }

        const float* As = smem + stg * GSTAGE_W;
        const float* Bs = As + GA_STAGE;

#pragma unroll
        for (int kk = 0; kk < 4; kk++) {
            const int kb = kk * 8;
            uint32_t aR[4][4], bR[4][2];
#pragma unroll
            for (int mi = 0; mi < 4; mi++) {
                const int m0 = wm0 + mi * 16;
                aR[mi][0] = f2tf32(As[(m0 + gid) * GAS_W + kb + tig]);
                aR[mi][1] = f2tf32(As[(m0 + gid + 8) * GAS_W + kb + tig]);
                aR[mi][2] = f2tf32(As[(m0 + gid) * GAS_W + kb + tig + 4]);
                aR[mi][3] = f2tf32(As[(m0 + gid + 8) * GAS_W + kb + tig + 4]);
            }
#pragma unroll
            for (int ni = 0; ni < 4; ni++) {
                const int n0 = wn0 + ni * 8;
                bR[ni][0] = f2tf32(Bs[(kb + tig) * GBS_W + n0 + gid]);
                bR[ni][1] = f2tf32(Bs[(kb + tig + 4) * GBS_W + n0 + gid]);
            }
#pragma unroll
            for (int mi = 0; mi < 4; mi++)
#pragma unroll
                for (int ni = 0; ni < 4; ni++) {
                    asm volatile(
                        "mma.sync.aligned.m16n8k8.row.col.f32.tf32.tf32.f32 "
                        "{%0,%1,%2,%3}, {%4,%5,%6,%7}, {%8,%9}, {%0,%1,%2,%3};"
                        : "+f"(c[mi][ni][0]), "+f"(c[mi][ni][1]),
                          "+f"(c[mi][ni][2]), "+f"(c[mi][ni][3])
                        : "r"(aR[mi][0]), "r"(aR[mi][1]), "r"(aR[mi][2]), "r"(aR[mi][3]),
                          "r"(bR[ni][0]), "r"(bR[ni][1]));
                }
        }

        if (++stg == 3) stg = 0;
    }

#pragma unroll
    for (int mi = 0; mi < 4; mi++) {
        const int m0 = wm0 + mi * 16;
#pragma unroll
        for (int ni = 0; ni < 4; ni++) {
            const int n0 = wn0 + ni * 8 + tig * 2;
            *(float2*)(Cb + (size_t)(m0 + gid) * N + n0) =
                make_float2(c[mi][ni][0], c[mi][ni][1]);
            *(float2*)(Cb + (size_t)(m0 + gid + 8) * N + n0) =
                make_float2(c[mi][ni][2], c[mi][ni][3]);
        }
    }
}

// fused QKV: grid (32, 32); bx<16 -> Q, 16..23 -> K, 24..31 -> V
__global__ __launch_bounds__(256, 2) void qkv_gemm(
    const float* __restrict__ X,
    const float* __restrict__ Wq, const float* __restrict__ Wk,
    const float* __restrict__ Wv)
{
    const int bx = blockIdx.x, by = blockIdx.y;
    const float* B; float* C; int N; int lbx;
    if (bx < 16)      { B = Wq; C = g_Q; N = NH * HD;  lbx = bx; }
    else if (bx < 24) { B = Wk; C = g_K; N = NKV * HD; lbx = bx - 16; }
    else              { B = Wv; C = g_V; N = NKV * HD; lbx = bx - 24; }
    gemm_core(X + (size_t)by * 128 * HIDDEN,
              B + (size_t)lbx * 128,
              C + (size_t)by * 128 * N + (size_t)lbx * 128,
              N, HIDDEN);
}

__global__ __launch_bounds__(256, 2) void wo_gemm(
    const float* __restrict__ Wo, float* __restrict__ out)
{
    const int bx = blockIdx.x, by = blockIdx.y;
    gemm_core(g_AO + (size_t)by * 128 * (NH * HD),
              Wo + (size_t)bx * 128,
              out + (size_t)by * 128 * HIDDEN + (size_t)bx * 128,
              HIDDEN, NH * HD);
}

// ---------------- RoPE (in place on g_Q, g_K) ----------------
__global__ void rope_kernel(const float* __restrict__ cosb,
                            const float* __restrict__ sinb)
{
    const int s = blockIdx.x;
    const float* cs = cosb + (size_t)s * HD;
    const float* sn = sinb + (size_t)s * HD;
    for (int idx = threadIdx.x; idx < (NH + NKV) * 64; idx += blockDim.x) {
        const int head = idx >> 6;
        const int d = idx & 63;
        const float c = cs[d];
        const float sv = sn[d];
        float* base;
        if (head < NH)
            base = g_Q + (size_t)s * (NH * HD) + head * HD;
        else
            base = g_K + (size_t)s * (NKV * HD) + (head - NH) * HD;
        const float x1 = base[d];
        const float x2 = base[d + 64];
        base[d]      = x1 * c - x2 * sv;
        base[d + 64] = x2 * c + x1 * sv;
    }
}

// ---------------- TF32 tensor-core flash attention ----------------
#define KS_AT 132   // mod 32 = 4
#define VS_AT 136   // mod 32 = 8
#define PS_AT 68    // mod 32 = 4

extern __shared__ float sm_attn[];

__global__ __launch_bounds__(128, 2) void attn_mma()
{
    float*    Qs = sm_attn;
    uint32_t* Ks = (uint32_t*)sm_attn;
    uint32_t* Vs = (uint32_t*)(sm_attn + 64 * KS_AT);
    uint32_t* Ps = (uint32_t*)(sm_attn + 64 * (KS_AT + VS_AT));

    const int qb = blockIdx.x;
    const int h  = blockIdx.y;
    const int kvh = h >> 1;
    const int q0 = qb * 64;
    const int tid = threadIdx.x;
    const int lane = tid & 31;
    const int w = tid >> 5;
    const int gid = lane >> 2;
    const int tig = lane & 3;

    const float* Qg = g_Q + (size_t)q0 * (NH * HD) + h * HD;
    for (int i = tid; i < 64 * HD / 4; i += 128) {
        const int r = i >> 5;
        const int d4 = (i & 31) * 4;
        float4 v = *(const float4*)(Qg + (size_t)r * (NH * HD) + d4);
        *(float4*)&Qs[r * KS_AT + d4] = v;
    }
    __syncthreads();

    uint32_t qa[16][4];
    const int qr0 = 16 * w + gid;
#pragma unroll
    for (int c = 0; c < 16; c++) {
        qa[c][0] = f2tf32(Qs[qr0 * KS_AT + 8 * c + tig]);
        qa[c][1] = f2tf32(Qs[(qr0 + 8) * KS_AT + 8 * c + tig]);
        qa[c][2] = f2tf32(Qs[qr0 * KS_AT + 8 * c + tig + 4]);
        qa[c][3] = f2tf32(Qs[(qr0 + 8) * KS_AT + 8 * c + tig + 4]);
    }

    float oacc[16][4];
#pragma unroll
    for (int ni = 0; ni < 16; ni++)
#pragma unroll
        for (int r = 0; r < 4; r++) oacc[ni][r] = 0.f;
    float lsum[2] = {0.f, 0.f};

    int lo = q0 - (WINDOW - 1);
    if (lo < 0) lo = 0;
    const int kb_lo = lo / 64;

    for (int kb = kb_lo; kb <= qb; kb++) {
        const int k0 = kb * 64;
        const float* Kg = g_K + (size_t)k0 * (NKV * HD) + kvh * HD;
        const float* Vg = g_V + (size_t)k0 * (NKV * HD) + kvh * HD;

        __syncthreads();
        for (int i = tid; i < 64 * HD / 4; i += 128) {
            const int r = i >> 5;
            const int d4 = (i & 31) * 4;
            float4 kv = *(const float4*)(Kg + (size_t)r * (NKV * HD) + d4);
            uint4 kt = make_uint4(f2tf32(kv.x), f2tf32(kv.y), f2tf32(kv.z), f2tf32(kv.w));
            *(uint4*)&Ks[r * KS_AT + d4] = kt;
            float4 vv = *(const float4*)(Vg + (size_t)r * (NKV * HD) + d4);
            uint4 vt = make_uint4(f2tf32(vv.x), f2tf32(vv.y), f2tf32(vv.z), f2tf32(vv.w));
            *(uint4*)&Vs[r * VS_AT + d4] = vt;
        }
        __syncthreads();

        float sc[8][4];
#pragma unroll
        for (int ni = 0; ni < 8; ni++)
#pragma unroll
            for (int r = 0; r < 4; r++) sc[ni][r] = 0.f;

#pragma unroll
        for (int c = 0; c < 16; c++) {
#pragma unroll
            for (int ni = 0; ni < 8; ni++) {
                uint32_t b0 = Ks[(8 * ni + gid) * KS_AT + 8 * c + tig];
                uint32_t b1 = Ks[(8 * ni + gid) * KS_AT + 8 * c + tig + 4];
                asm volatile(
                    "mma.sync.aligned.m16n8k8.row.col.f32.tf32.tf32.f32 "
                    "{%0,%1,%2,%3}, {%4,%5,%6,%7}, {%8,%9}, {%0,%1,%2,%3};"
                    : "+f"(sc[ni][0]), "+f"(sc[ni][1]), "+f"(sc[ni][2]), "+f"(sc[ni][3])
                    : "r"(qa[c][0]), "r"(qa[c][1]), "r"(qa[c][2]), "r"(qa[c][3]),
                      "r"(b0), "r"(b1));
            }
        }

        const bool full = (k0 + 63 <= q0) && (q0 + 63 - k0 < WINDOW);
        float lp0 = 0.f, lp1 = 0.f;
#pragma unroll
        for (int ni = 0; ni < 8; ni++) {
#pragma unroll
            for (int r2 = 0; r2 < 2; r2++) {
#pragma unroll
                for (int cc = 0; cc < 2; cc++) {
                    const float raw = sc[ni][r2 * 2 + cc];
                    const int rg = q0 + qr0 + r2 * 8;
                    const int kg = k0 + 8 * ni + 2 * tig + cc;
                    float z = raw * (SCALING / SOFTCAP);
                    float t;
                    if (fabsf(z) < 0.3f) {
                        const float z2 = z * z;
                        t = z * (1.f + z2 * (-0.3333333333f +
                              z2 * (0.1333333333f - 0.05396825397f * z2)));
                    } else {
                        t = tanhf(z);
                    }
                    float p = __expf(t * SOFTCAP);
                    if (!full && (kg > rg || rg - kg >= WINDOW)) p = 0.f;
                    const uint32_t pt = f2tf32(p);
                    const float prnd = __uint_as_float(pt);
                    if (r2 == 0) lp0 += prnd; else lp1 += prnd;
                    Ps[(qr0 + r2 * 8) * PS_AT + 8 * ni + 2 * tig + cc] = pt;
                }
            }
        }
        lp0 += __shfl_xor_sync(0xffffffffu, lp0, 1);
        lp0 += __shfl_xor_sync(0xffffffffu, lp0, 2);
        lp1 += __shfl_xor_sync(0xffffffffu, lp1, 1);
        lp1 += __shfl_xor_sync(0xffffffffu, lp1, 2);
        lsum[0] += lp0;
        lsum[1] += lp1;
        __syncwarp();

#pragma unroll
        for (int c = 0; c < 8; c++) {
            uint32_t pa[4];
            pa[0] = Ps[qr0 * PS_AT + 8 * c + tig];
            pa[1] = Ps[(qr0 + 8) * PS_AT + 8 * c + tig];
            pa[2] = Ps[qr0 * PS_AT + 8 * c + tig + 4];
            pa[3] = Ps[(qr0 + 8) * PS_AT + 8 * c + tig + 4];
#pragma unroll
            for (int ni = 0; ni < 16; ni++) {
                uint32_t b0 = Vs[(8 * c + tig) * VS_AT + 8 * ni + gid];
                uint32_t b1 = Vs[(8 * c + tig + 4) * VS_AT + 8 * ni + gid];
                asm volatile(
                    "mma.sync.aligned.m16n8k8.row.col.f32.tf32.tf32.f32 "
                    "{%0,%1,%2,%3}, {%4,%5,%6,%7}, {%8,%9}, {%0,%1,%2,%3};"
                    : "+f"(oacc[ni][0]), "+f"(oacc[ni][1]),
                      "+f"(oacc[ni][2]), "+f"(oacc[ni][3])
                    : "r"(pa[0]), "r"(pa[1]), "r"(pa[2]), "r"(pa[3]),
                      "r"(b0), "r"(b1));
            }
        }
        __syncwarp();
    }

    const float inv0 = 1.0f / lsum[0];
    const float inv1 = 1.0f / lsum[1];
    float* out0 = g_AO + (size_t)(q0 + qr0) * (NH * HD) + h * HD;
    float* out1 = g_AO + (size_t)(q0 + qr0 + 8) * (NH * HD) + h * HD;
#pragma unroll
    for (int ni = 0; ni < 16; ni++) {
        const int n0 = 8 * ni + 2 * tig;
        *(float2*)(out0 + n0) = make_float2(oacc[ni][0] * inv0, oacc[ni][1] * inv0);
        *(float2*)(out1 + n0) = make_float2(oacc[ni][2] * inv1, oacc[ni][3] * inv1);
    }
}

// ---------------- launch ----------------
extern "C" void kernel_launch(void* const* d_in, const int* in_sizes, int n_in,
                              void* d_out, int out_size)
{
    const float* hs   = (const float*)d_in[0];
    const float* cosb = (const float*)d_in[1];
    const float* sinb = (const float*)d_in[2];
    // d_in[3] attention_mask: computed analytically, never read
    const float* Wq = (const float*)d_in[4];
    const float* Wk = (const float*)d_in[5];
    const float* Wv = (const float*)d_in[6];
    const float* Wo = (const float*)d_in[7];
    float* out = (float*)d_out;

    cudaFuncSetAttribute(qkv_gemm, cudaFuncAttributeMaxDynamicSharedMemorySize, GSMEM_BYTES);
    cudaFuncSetAttribute(wo_gemm, cudaFuncAttributeMaxDynamicSharedMemorySize, GSMEM_BYTES);

    qkv_gemm<<<dim3(32, SEQ / 128), 256, GSMEM_BYTES>>>(hs, Wq, Wk, Wv);

    rope_kernel<<<SEQ, 256>>>(cosb, sinb);

    const size_t smem_attn = (size_t)64 * (KS_AT + VS_AT + PS_AT) * sizeof(float);
    cudaFuncSetAttribute(attn_mma, cudaFuncAttributeMaxDynamicSharedMemorySize,
                         (int)smem_attn);
    attn_mma<<<dim3(SEQ / 64, NH), 128, smem_attn>>>();

    wo_gemm<<<dim3(HIDDEN / 128, SEQ / 128), 256, GSMEM_BYTES>>>(Wo, out);
}

// round 14
// speedup vs baseline: 1.0523x; 1.0523x over previous
#include <cuda_runtime.h>
#include <cstdint>

#define SEQ 4096
#define HIDDEN 2048
#define NH 16
#define NKV 8
#define HD 128
#define WINDOW 1024
#define SCALING 0.08838834764831845f  /* 128^-0.5 */
#define SOFTCAP 50.0f

// ---------------- scratch (no allocations allowed) ----------------
__device__ float g_Q[SEQ * NH * HD];    // 32 MB
__device__ float g_K[SEQ * NKV * HD];   // 16 MB
__device__ float g_V[SEQ * NKV * HD];   // 16 MB
__device__ float g_AO[SEQ * NH * HD];   // 32 MB (written pre-rounded to tf32)
// pre-rounded tf32 operands for the GEMMs
__device__ float g_Xr[SEQ * HIDDEN];        // 32 MB
__device__ float g_Wqr[HIDDEN * NH * HD];   // 16 MB
__device__ float g_Wkr[HIDDEN * NKV * HD];  // 8 MB
__device__ float g_Wvr[HIDDEN * NKV * HD];  // 8 MB
__device__ float g_Wor[NH * HD * HIDDEN];   // 16 MB

__device__ __forceinline__ uint32_t f2tf32(float x) {
    uint32_t r;
    asm("cvt.rna.tf32.f32 %0, %1;" : "=r"(r) : "f"(x));
    return r;
}
__device__ __forceinline__ float rnd_tf32(float x) {
    return __uint_as_float(f2tf32(x));
}

__device__ __forceinline__ void cp16(uint32_t s, const void* g) {
    asm volatile("cp.async.cg.shared.global [%0], [%1], 16;" :: "r"(s), "l"(g) : "memory");
}
__device__ __forceinline__ void cp_commit() {
    asm volatile("cp.async.commit_group;" ::: "memory");
}
__device__ __forceinline__ void cp_wait1() {
    asm volatile("cp.async.wait_group 1;" ::: "memory");
}

// ---------------- tf32 pre-round copy (X, W*) ----------------
__global__ void round_copy(const float4* __restrict__ src,
                           float4* __restrict__ dst, int n4)
{
    int i = blockIdx.x * blockDim.x + threadIdx.x;
    if (i < n4) {
        float4 v = src[i];
        v.x = rnd_tf32(v.x); v.y = rnd_tf32(v.y);
        v.z = rnd_tf32(v.z); v.w = rnd_tf32(v.w);
        dst[i] = v;
    }
}

// ---------------- cp.async 2-stage pipelined TF32 GEMM core ----------------
// Operands are PRE-ROUNDED to tf32 in gmem -> no cvt in the inner loop
// (HMMA's operand truncation is the identity on pre-rounded values).
// C[128,128] block of C[M,N] = A[M,K] @ B[K,N], row-major.
// 256 thr (8 warps, 2x4), BK=32, 2-stage cp.async ring.
// As [m][k] stride 36 (mod32=4 -> A frags conflict-free)
// Bs [k][n] stride 136 (mod32=8 -> B frags conflict-free)
#define GAS_W 36
#define GBS_W 136
#define GA_STAGE (128 * GAS_W)          // 4608 words
#define GB_STAGE (32 * GBS_W)           // 4352 words
#define GSTAGE_W (GA_STAGE + GB_STAGE)  // 8960 words
#define GSMEM_BYTES (2 * GSTAGE_W * 4)  // 71680 B

__device__ __forceinline__ void gemm_core(
    const float* __restrict__ Ab,   // A + by*128*K   (tf32-rounded)
    const float* __restrict__ Bb,   // B + bx*128     (tf32-rounded)
    float* __restrict__ Cb,         // C + by*128*N + bx*128
    int N, int K)
{
    extern __shared__ float smem[];
    const uint32_t sb = (uint32_t)__cvta_generic_to_shared(smem);

    const int tid  = threadIdx.x;
    const int lane = tid & 31;
    const int gid  = lane >> 2;
    const int tig  = lane & 3;
    const int wid  = tid >> 5;
    const int wm0  = (wid >> 2) * 64;
    const int wn0  = (wid & 3) * 32;

    float c[4][4][4];
#pragma unroll
    for (int mi = 0; mi < 4; mi++)
#pragma unroll
        for (int ni = 0; ni < 4; ni++)
#pragma unroll
            for (int r = 0; r < 4; r++) c[mi][ni][r] = 0.f;

    const int KT = K / 32;

    auto issue = [&](int stg, int k0) {
        const uint32_t as = sb + (uint32_t)stg * GSTAGE_W * 4;
        const uint32_t bs = as + GA_STAGE * 4;
#pragma unroll
        for (int i = 0; i < 4; i++) {
            const int t = tid + i * 256;
            const int m = t >> 3, j = t & 7;
            cp16(as + (uint32_t)(m * GAS_W + 4 * j) * 4,
                 Ab + (size_t)m * K + k0 + 4 * j);
        }
#pragma unroll
        for (int i = 0; i < 4; i++) {
            const int t = tid + i * 256;
            const int r = t >> 5, cc = t & 31;
            cp16(bs + (uint32_t)(r * GBS_W + 4 * cc) * 4,
                 Bb + (size_t)(k0 + r) * N + 4 * cc);
        }
        cp_commit();
    };

    issue(0, 0);

    for (int kt = 0; kt < KT; kt++) {
        if (kt + 1 < KT) issue((kt + 1) & 1, (kt + 1) * 32);
        else             cp_commit();          // empty group keeps wait count honest
        cp_wait1();
        __syncthreads();

        const uint32_t* As = (const uint32_t*)(smem + (kt & 1) * GSTAGE_W);
        const uint32_t* Bs = As + GA_STAGE;

#pragma unroll
        for (int kk = 0; kk < 4; kk++) {
            const int kb = kk * 8;
            uint32_t aR[4][4], bR[4][2];
#pragma unroll
            for (int mi = 0; mi < 4; mi++) {
                const int m0 = wm0 + mi * 16;
                aR[mi][0] = As[(m0 + gid) * GAS_W + kb + tig];
                aR[mi][1] = As[(m0 + gid + 8) * GAS_W + kb + tig];
                aR[mi][2] = As[(m0 + gid) * GAS_W + kb + tig + 4];
                aR[mi][3] = As[(m0 + gid + 8) * GAS_W + kb + tig + 4];
            }
#pragma unroll
            for (int ni = 0; ni < 4; ni++) {
                const int n0 = wn0 + ni * 8;
                bR[ni][0] = Bs[(kb + tig) * GBS_W + n0 + gid];
                bR[ni][1] = Bs[(kb + tig + 4) * GBS_W + n0 + gid];
            }
#pragma unroll
            for (int mi = 0; mi < 4; mi++)
#pragma unroll
                for (int ni = 0; ni < 4; ni++) {
                    asm volatile(
                        "mma.sync.aligned.m16n8k8.row.col.f32.tf32.tf32.f32 "
                        "{%0,%1,%2,%3}, {%4,%5,%6,%7}, {%8,%9}, {%0,%1,%2,%3};"
                        : "+f"(c[mi][ni][0]), "+f"(c[mi][ni][1]),
                          "+f"(c[mi][ni][2]), "+f"(c[mi][ni][3])
                        : "r"(aR[mi][0]), "r"(aR[mi][1]), "r"(aR[mi][2]), "r"(aR[mi][3]),
                          "r"(bR[ni][0]), "r"(bR[ni][1]));
                }
        }
        __syncthreads();   // all reads of this stage done before it is re-filled
    }

#pragma unroll
    for (int mi = 0; mi < 4; mi++) {
        const int m0 = wm0 + mi * 16;
#pragma unroll
        for (int ni = 0; ni < 4; ni++) {
            const int n0 = wn0 + ni * 8 + tig * 2;
            *(float2*)(Cb + (size_t)(m0 + gid) * N + n0) =
                make_float2(c[mi][ni][0], c[mi][ni][1]);
            *(float2*)(Cb + (size_t)(m0 + gid + 8) * N + n0) =
                make_float2(c[mi][ni][2], c[mi][ni][3]);
        }
    }
}

// fused QKV: grid (32, 32); bx<16 -> Q, 16..23 -> K, 24..31 -> V
__global__ __launch_bounds__(256, 2) void qkv_gemm()
{
    const int bx = blockIdx.x, by = blockIdx.y;
    const float* B; float* C; int N; int lbx;
    if (bx < 16)      { B = g_Wqr; C = g_Q; N = NH * HD;  lbx = bx; }
    else if (bx < 24) { B = g_Wkr; C = g_K; N = NKV * HD; lbx = bx - 16; }
    else              { B = g_Wvr; C = g_V; N = NKV * HD; lbx = bx - 24; }
    gemm_core(g_Xr + (size_t)by * 128 * HIDDEN,
              B + (size_t)lbx * 128,
              C + (size_t)by * 128 * N + (size_t)lbx * 128,
              N, HIDDEN);
}

__global__ __launch_bounds__(256, 2) void wo_gemm(float* __restrict__ out)
{
    const int bx = blockIdx.x, by = blockIdx.y;
    gemm_core(g_AO + (size_t)by * 128 * (NH * HD),
              g_Wor + (size_t)bx * 128,
              out + (size_t)by * 128 * HIDDEN + (size_t)bx * 128,
              HIDDEN, NH * HD);
}

// ---------------- RoPE (in place on g_Q, g_K) ----------------
__global__ void rope_kernel(const float* __restrict__ cosb,
                            const float* __restrict__ sinb)
{
    const int s = blockIdx.x;
    const float* cs = cosb + (size_t)s * HD;
    const float* sn = sinb + (size_t)s * HD;
    for (int idx = threadIdx.x; idx < (NH + NKV) * 64; idx += blockDim.x) {
        const int head = idx >> 6;
        const int d = idx & 63;
        const float c = cs[d];
        const float sv = sn[d];
        float* base;
        if (head < NH)
            base = g_Q + (size_t)s * (NH * HD) + head * HD;
        else
            base = g_K + (size_t)s * (NKV * HD) + (head - NH) * HD;
        const float x1 = base[d];
        const float x2 = base[d + 64];
        base[d]      = x1 * c - x2 * sv;
        base[d + 64] = x2 * c + x1 * sv;
    }
}

// ---------------- TF32 tensor-core flash attention ----------------
#define KS_AT 132   // mod 32 = 4
#define VS_AT 136   // mod 32 = 8
#define PS_AT 68    // mod 32 = 4

extern __shared__ float sm_attn[];

__global__ __launch_bounds__(128, 2) void attn_mma()
{
    float*    Qs = sm_attn;
    uint32_t* Ks = (uint32_t*)sm_attn;
    uint32_t* Vs = (uint32_t*)(sm_attn + 64 * KS_AT);
    uint32_t* Ps = (uint32_t*)(sm_attn + 64 * (KS_AT + VS_AT));

    const int qb = blockIdx.x;
    const int h  = blockIdx.y;
    const int kvh = h >> 1;
    const int q0 = qb * 64;
    const int tid = threadIdx.x;
    const int lane = tid & 31;
    const int w = tid >> 5;
    const int gid = lane >> 2;
    const int tig = lane & 3;

    const float* Qg = g_Q + (size_t)q0 * (NH * HD) + h * HD;
    for (int i = tid; i < 64 * HD / 4; i += 128) {
        const int r = i >> 5;
        const int d4 = (i & 31) * 4;
        float4 v = *(const float4*)(Qg + (size_t)r * (NH * HD) + d4);
        *(float4*)&Qs[r * KS_AT + d4] = v;
    }
    __syncthreads();

    uint32_t qa[16][4];
    const int qr0 = 16 * w + gid;
#pragma unroll
    for (int c = 0; c < 16; c++) {
        qa[c][0] = f2tf32(Qs[qr0 * KS_AT + 8 * c + tig]);
        qa[c][1] = f2tf32(Qs[(qr0 + 8) * KS_AT + 8 * c + tig]);
        qa[c][2] = f2tf32(Qs[qr0 * KS_AT + 8 * c + tig + 4]);
        qa[c][3] = f2tf32(Qs[(qr0 + 8) * KS_AT + 8 * c + tig + 4]);
    }

    float oacc[16][4];
#pragma unroll
    for (int ni = 0; ni < 16; ni++)
#pragma unroll
        for (int r = 0; r < 4; r++) oacc[ni][r] = 0.f;
    float lsum[2] = {0.f, 0.f};

    int lo = q0 - (WINDOW - 1);
    if (lo < 0) lo = 0;
    const int kb_lo = lo / 64;

    for (int kb = kb_lo; kb <= qb; kb++) {
        const int k0 = kb * 64;
        const float* Kg = g_K + (size_t)k0 * (NKV * HD) + kvh * HD;
        const float* Vg = g_V + (size_t)k0 * (NKV * HD) + kvh * HD;

        __syncthreads();
        for (int i = tid; i < 64 * HD / 4; i += 128) {
            const int r = i >> 5;
            const int d4 = (i & 31) * 4;
            float4 kv = *(const float4*)(Kg + (size_t)r * (NKV * HD) + d4);
            uint4 kt = make_uint4(f2tf32(kv.x), f2tf32(kv.y), f2tf32(kv.z), f2tf32(kv.w));
            *(uint4*)&Ks[r * KS_AT + d4] = kt;
            float4 vv = *(const float4*)(Vg + (size_t)r * (NKV * HD) + d4);
            uint4 vt = make_uint4(f2tf32(vv.x), f2tf32(vv.y), f2tf32(vv.z), f2tf32(vv.w));
            *(uint4*)&Vs[r * VS_AT + d4] = vt;
        }
        __syncthreads();

        float sc[8][4];
#pragma unroll
        for (int ni = 0; ni < 8; ni++)
#pragma unroll
            for (int r = 0; r < 4; r++) sc[ni][r] = 0.f;

#pragma unroll
        for (int c = 0; c < 16; c++) {
#pragma unroll
            for (int ni = 0; ni < 8; ni++) {
                uint32_t b0 = Ks[(8 * ni + gid) * KS_AT + 8 * c + tig];
                uint32_t b1 = Ks[(8 * ni + gid) * KS_AT + 8 * c + tig + 4];
                asm volatile(
                    "mma.sync.aligned.m16n8k8.row.col.f32.tf32.tf32.f32 "
                    "{%0,%1,%2,%3}, {%4,%5,%6,%7}, {%8,%9}, {%0,%1,%2,%3};"
                    : "+f"(sc[ni][0]), "+f"(sc[ni][1]), "+f"(sc[ni][2]), "+f"(sc[ni][3])
                    : "r"(qa[c][0]), "r"(qa[c][1]), "r"(qa[c][2]), "r"(qa[c][3]),
                      "r"(b0), "r"(b1));
            }
        }

        const bool full = (k0 + 63 <= q0) && (q0 + 63 - k0 < WINDOW);
        float lp0 = 0.f, lp1 = 0.f;
#pragma unroll
        for (int ni = 0; ni < 8; ni++) {
#pragma unroll
            for (int r2 = 0; r2 < 2; r2++) {
#pragma unroll
                for (int cc = 0; cc < 2; cc++) {
                    const float raw = sc[ni][r2 * 2 + cc];
                    const int rg = q0 + qr0 + r2 * 8;
                    const int kg = k0 + 8 * ni + 2 * tig + cc;
                    float z = raw * (SCALING / SOFTCAP);
                    float t;
                    if (fabsf(z) < 0.3f) {
                        const float z2 = z * z;
                        t = z * (1.f + z2 * (-0.3333333333f +
                              z2 * (0.1333333333f - 0.05396825397f * z2)));
                    } else {
                        t = tanhf(z);
                    }
                    float p = __expf(t * SOFTCAP);
                    if (!full && (kg > rg || rg - kg >= WINDOW)) p = 0.f;
                    const uint32_t pt = f2tf32(p);
                    const float prnd = __uint_as_float(pt);
                    if (r2 == 0) lp0 += prnd; else lp1 += prnd;
                    Ps[(qr0 + r2 * 8) * PS_AT + 8 * ni + 2 * tig + cc] = pt;
                }
            }
        }
        lp0 += __shfl_xor_sync(0xffffffffu, lp0, 1);
        lp0 += __shfl_xor_sync(0xffffffffu, lp0, 2);
        lp1 += __shfl_xor_sync(0xffffffffu, lp1, 1);
        lp1 += __shfl_xor_sync(0xffffffffu, lp1, 2);
        lsum[0] += lp0;
        lsum[1] += lp1;
        __syncwarp();

#pragma unroll
        for (int c = 0; c < 8; c++) {
            uint32_t pa[4];
            pa[0] = Ps[qr0 * PS_AT + 8 * c + tig];
            pa[1] = Ps[(qr0 + 8) * PS_AT + 8 * c + tig];
            pa[2] = Ps[qr0 * PS_AT + 8 * c + tig + 4];
            pa[3] = Ps[(qr0 + 8) * PS_AT + 8 * c + tig + 4];
#pragma unroll
            for (int ni = 0; ni < 16; ni++) {
                uint32_t b0 = Vs[(8 * c + tig) * VS_AT + 8 * ni + gid];
                uint32_t b1 = Vs[(8 * c + tig + 4) * VS_AT + 8 * ni + gid];
                asm volatile(
                    "mma.sync.aligned.m16n8k8.row.col.f32.tf32.tf32.f32 "
                    "{%0,%1,%2,%3}, {%4,%5,%6,%7}, {%8,%9}, {%0,%1,%2,%3};"
                    : "+f"(oacc[ni][0]), "+f"(oacc[ni][1]),
                      "+f"(oacc[ni][2]), "+f"(oacc[ni][3])
                    : "r"(pa[0]), "r"(pa[1]), "r"(pa[2]), "r"(pa[3]),
                      "r"(b0), "r"(b1));
            }
        }
        __syncwarp();
    }

    // write AO pre-rounded to tf32 so wo_gemm needs no cvt (same bits as
    // the old in-loop cvt.rna on raw AO -> results unchanged)
    const float inv0 = 1.0f / lsum[0];
    const float inv1 = 1.0f / lsum[1];
    float* out0 = g_AO + (size_t)(q0 + qr0) * (NH * HD) + h * HD;
    float* out1 = g_AO + (size_t)(q0 + qr0 + 8) * (NH * HD) + h * HD;
#pragma unroll
    for (int ni = 0; ni < 16; ni++) {
        const int n0 = 8 * ni + 2 * tig;
        *(float2*)(out0 + n0) =
            make_float2(rnd_tf32(oacc[ni][0] * inv0), rnd_tf32(oacc[ni][1] * inv0));
        *(float2*)(out1 + n0) =
            make_float2(rnd_tf32(oacc[ni][2] * inv1), rnd_tf32(oacc[ni][3] * inv1));
    }
}

// ---------------- launch ----------------
extern "C" void kernel_launch(void* const* d_in, const int* in_sizes, int n_in,
                              void* d_out, int out_size)
{
    const float* hs   = (const float*)d_in[0];
    const float* cosb = (const float*)d_in[1];
    const float* sinb = (const float*)d_in[2];
    // d_in[3] attention_mask: computed analytically, never read
    const float* Wq = (const float*)d_in[4];
    const float* Wk = (const float*)d_in[5];
    const float* Wv = (const float*)d_in[6];
    const float* Wo = (const float*)d_in[7];
    float* out = (float*)d_out;

    float *xr, *wqr, *wkr, *wvr, *wor;
    cudaGetSymbolAddress((void**)&xr,  g_Xr);
    cudaGetSymbolAddress((void**)&wqr, g_Wqr);
    cudaGetSymbolAddress((void**)&wkr, g_Wkr);
    cudaGetSymbolAddress((void**)&wvr, g_Wvr);
    cudaGetSymbolAddress((void**)&wor, g_Wor);

    // pre-round all GEMM operands to tf32 (RNA) once
    const int TPB = 256;
    round_copy<<<(SEQ * HIDDEN / 4 + TPB - 1) / TPB, TPB>>>(
        (const float4*)hs, (float4*)xr, SEQ * HIDDEN / 4);
    round_copy<<<(HIDDEN * NH * HD / 4 + TPB - 1) / TPB, TPB>>>(
        (const float4*)Wq, (float4*)wqr, HIDDEN * NH * HD / 4);
    round_copy<<<(HIDDEN * NKV * HD / 4 + TPB - 1) / TPB, TPB>>>(
        (const float4*)Wk, (float4*)wkr, HIDDEN * NKV * HD / 4);
    round_copy<<<(HIDDEN * NKV * HD / 4 + TPB - 1) / TPB, TPB>>>(
        (const float4*)Wv, (float4*)wvr, HIDDEN * NKV * HD / 4);
    round_copy<<<(NH * HD * HIDDEN / 4 + TPB - 1) / TPB, TPB>>>(
        (const float4*)Wo, (float4*)wor, NH * HD * HIDDEN / 4);

    cudaFuncSetAttribute(qkv_gemm, cudaFuncAttributeMaxDynamicSharedMemorySize, GSMEM_BYTES);
    cudaFuncSetAttribute(wo_gemm, cudaFuncAttributeMaxDynamicSharedMemorySize, GSMEM_BYTES);

    qkv_gemm<<<dim3(32, SEQ / 128), 256, GSMEM_BYTES>>>();

    rope_kernel<<<SEQ, 256>>>(cosb, sinb);

    const size_t smem_attn = (size_t)64 * (KS_AT + VS_AT + PS_AT) * sizeof(float);
    cudaFuncSetAttribute(attn_mma, cudaFuncAttributeMaxDynamicSharedMemorySize,
                         (int)smem_attn);
    attn_mma<<<dim3(SEQ / 64, NH), 128, smem_attn>>>();

    wo_gemm<<<dim3(HIDDEN / 128, SEQ / 128), 256, GSMEM_BYTES>>>(out);
}